// round 6
// baseline (speedup 1.0000x reference)
#include <cuda_runtime.h>

#define HID   128
#define SEQ   512
#define BATCH 1024
#define BT    7
#define NCTA  147
#define NTHR  384

#define HB    (BT*HID)            // 896
#define S_H   0                   // h double buffer: 2*HB
#define S_R   (2*HB)              // r gate values: HB
#define S_Z   (S_R + HB)          // z gate values: HB
#define S_V   (S_Z + HB)          // v double buffer: 2*14
#define S_P   (S_V + 28)          // x_pred partials: 2 bufs * 4 warps * 14
#define SMF   (S_P + 112)

typedef unsigned long long u64t;

__device__ __forceinline__ u64t pk2(float lo, float hi){
  u64t r; asm("mov.b64 %0,{%1,%2};":"=l"(r):"f"(lo),"f"(hi)); return r;
}
__device__ __forceinline__ float psum(u64t p){
  float lo,hi; asm("mov.b64 {%0,%1},%2;":"=f"(lo),"=f"(hi):"l"(p)); return lo+hi;
}
__device__ __forceinline__ void fma2(u64t &d, u64t a, u64t b){
  asm("fma.rn.f32x2 %0,%1,%2,%0;":"+l"(d):"l"(a),"l"(b));
}
__device__ __forceinline__ float sigm(float x){ return __fdividef(1.f,1.f+__expf(-x)); }
__device__ __forceinline__ float tanh_f(float x){ return __fdividef(2.f,1.f+__expf(-2.f*x)) - 1.f; }

__global__ void dummy_kernel(){}

__global__ __launch_bounds__(NTHR,1) void gru_kernel(
  const float* __restrict__ v_seq, const float* __restrict__ W_ih,
  const float* __restrict__ W_hh,  const float* __restrict__ b_ih,
  const float* __restrict__ b_hh,  const float* __restrict__ W_out,
  const float* __restrict__ b_out, float* __restrict__ xpred)
{
  __shared__ float sm[SMF];
  const int tid  = threadIdx.x;
  const int t_   = tid & 127;          // row index within gate
  const int g    = tid >> 7;           // 0:r 1:z 2:n
  const int lane = tid & 31;
  const int wid  = tid >> 5;           // n-warps are 8..11 (one per SMSP)
  const int b0   = blockIdx.x * BT;
  const int grow = g*HID + t_;

  for (int i = tid; i < HB; i += NTHR) sm[S_H + i] = 0.f;   // h[buf0] = 0

  // ---- W_hh row for this thread -> 64 packed f32x2 registers (192KB/CTA total)
  u64t w[64];
  {
    const float4* wr4 = (const float4*)(W_hh + grow*HID);
    #pragma unroll
    for (int q = 0; q < 32; q++){
      float4 f = wr4[q];
      w[2*q]   = pk2(f.x, f.y);
      w[2*q+1] = pk2(f.z, f.w);
    }
  }

  // ---- per-thread scalar constants
  float cI = b_hh[grow];
  float cw0=0.f, cw1=0.f, xb=0.f, xw0=0.f, xw1=0.f, wo0=0.f, wo1=0.f;
  if (g < 2){                                 // r,z: fold x-projection into acc
    cI += b_ih[grow]; cw0 = W_ih[2*grow]; cw1 = W_ih[2*grow+1];
  } else {                                    // n: x-part stays outside r*hn
    xb  = b_ih[grow]; xw0 = W_ih[2*grow]; xw1 = W_ih[2*grow+1];
    wo0 = W_out[t_];  wo1 = W_out[HID + t_];
  }

  // ---- v loader / x_pred writer threads (tid < 14, these are r-threads)
  const int  bb = tid >> 1, comp = tid & 1;
  const int  gb = b0 + bb;
  const bool vact = (tid < 14);
  const bool uval = vact && (gb < BATCH);
  float boutv = 0.f, vreg = 0.f;
  if (vact){
    boutv = b_out[comp];
    sm[S_V + tid] = uval ? v_seq[(gb*SEQ + 0)*2 + comp] : 0.f;
    if (uval) vreg = v_seq[(gb*SEQ + 1)*2 + comp];
  }

  __syncthreads();

  for (int st = 0; st < SEQ; st++){
    const int cur = st & 1, nxt = cur ^ 1;

    // x_pred of previous step + publish v for next step (overlaps GEMM)
    if (vact){
      if (st > 0 && uval){
        const int rp = nxt;               // (st-1)&1
        float s = sm[S_P + rp*56 + tid]      + sm[S_P + rp*56 + 14 + tid]
                + sm[S_P + rp*56 + 28 + tid] + sm[S_P + rp*56 + 42 + tid] + boutv;
        xpred[(gb*SEQ + (st-1))*2 + comp] = s;
      }
      sm[S_V + nxt*14 + tid] = vreg;
    }

    // ---- acc init (r,z fold x-projection; n gets b_hh only)
    u64t acc[BT];
    #pragma unroll
    for (int b = 0; b < BT; b++){
      float v0 = sm[S_V + cur*14 + 2*b];
      float v1 = sm[S_V + cur*14 + 2*b + 1];
      acc[b] = pk2(cI + cw0*v0 + cw1*v1, 0.f);
    }

    // ---- GEMM: weights from registers, h broadcast from SMEM
    const ulonglong2* __restrict__ Hc = (const ulonglong2*)(sm + S_H + cur*HB);
    #pragma unroll
    for (int b = 0; b < BT; b++){
      #pragma unroll
      for (int kq = 0; kq < 32; kq++){
        ulonglong2 h = Hc[b*32 + kq];
        fma2(acc[b], w[2*kq],   h.x);
        fma2(acc[b], w[2*kq+1], h.y);
      }
    }

    // ---- r,z: activate and publish
    if (g < 2){
      float* dst = sm + (g == 0 ? S_R : S_Z);
      #pragma unroll
      for (int b = 0; b < BT; b++)
        dst[b*HID + t_] = sigm(psum(acc[b]));
    }
    __syncthreads();                       // barrier 1: r,z visible

    // ---- n-warps: gates, h update, x_pred partial reduce
    if (g == 2){
      #pragma unroll
      for (int b = 0; b < BT; b++){
        float hn = psum(acc[b]);
        float r  = sm[S_R + b*HID + t_];
        float z  = sm[S_Z + b*HID + t_];
        float v0 = sm[S_V + cur*14 + 2*b];
        float v1 = sm[S_V + cur*14 + 2*b + 1];
        float n  = tanh_f(xb + xw0*v0 + xw1*v1 + r*hn);
        float hp = sm[S_H + cur*HB + b*HID + t_];
        float h  = (1.f - z)*n + z*hp;
        sm[S_H + nxt*HB + b*HID + t_] = h;
        float p0 = wo0*h, p1 = wo1*h;
        p0 += __shfl_xor_sync(0xffffffffu, p0, 16);
        p1 += __shfl_xor_sync(0xffffffffu, p1, 16);
        float wv = (lane & 16) ? p1 : p0;
        #pragma unroll
        for (int off = 8; off > 0; off >>= 1)
          wv += __shfl_xor_sync(0xffffffffu, wv, off);
        if (lane == 0)  sm[S_P + cur*56 + (wid-8)*14 + 2*b]     = wv;
        if (lane == 16) sm[S_P + cur*56 + (wid-8)*14 + 2*b + 1] = wv;
      }
    }
    if (vact){                              // r-threads are idle here: prefetch v
      int s2 = st + 2;
      vreg = (uval && s2 < SEQ) ? v_seq[(gb*SEQ + s2)*2 + comp] : 0.f;
    }
    __syncthreads();                       // barrier 2: h/v/partials published
  }

  // final x_pred (st = SEQ-1, partials in P[1])
  if (uval){
    float s = sm[S_P + 56 + tid]      + sm[S_P + 56 + 14 + tid]
            + sm[S_P + 56 + 28 + tid] + sm[S_P + 56 + 42 + tid] + boutv;
    xpred[(gb*SEQ + (SEQ-1))*2 + comp] = s;
  }
}

// ---- kernel 2: residual MLP + physics violations (elementwise over B*S)
__global__ __launch_bounds__(256) void resid_kernel(
  const float* __restrict__ xpred, const float* __restrict__ x0,
  const float* __restrict__ v_seq,
  const float* __restrict__ W_r1, const float* __restrict__ b_r1,
  const float* __restrict__ W_r2, const float* __restrict__ b_r2,
  float* __restrict__ viol)
{
  __shared__ float w1[64*4], B1[64], w2[128], B2[2];
  int tid = threadIdx.x;
  if (tid < 256) w1[tid] = W_r1[tid];
  if (tid < 64)  B1[tid] = b_r1[tid];
  if (tid < 128) w2[tid] = W_r2[tid];
  if (tid < 2)   B2[tid] = b_r2[tid];
  __syncthreads();

  int idx = blockIdx.x*256 + tid;          // grid covers BATCH*SEQ exactly
  int b = idx >> 9, s = idx & (SEQ-1);
  float xp0, xp1;
  if (s == 0){ xp0 = x0[2*b];          xp1 = x0[2*b+1]; }
  else       { xp0 = xpred[(idx-1)*2]; xp1 = xpred[(idx-1)*2+1]; }
  float v0 = v_seq[idx*2], v1 = v_seq[idx*2+1];

  float a0 = B2[0], a1 = B2[1];
  #pragma unroll 8
  for (int h = 0; h < 64; h++){
    float hh = B1[h] + w1[4*h]*xp0 + w1[4*h+1]*xp1 + w1[4*h+2]*v0 + w1[4*h+3]*v1;
    hh = fmaxf(hh, 0.f);
    a0 += w2[h]*hh;
    a1 += w2[64+h]*hh;
  }
  float c0 = xpred[idx*2], c1 = xpred[idx*2+1];
  viol[idx*2]   = c0 - (xp0 + v0 + a0);
  viol[idx*2+1] = c1 - (xp1 + v1 + a1);
}

extern "C" void kernel_launch(void* const* d_in, const int* in_sizes, int n_in,
                              void* d_out, int out_size)
{
  const float* x0    = (const float*)d_in[0];
  const float* v_seq = (const float*)d_in[1];
  const float* W_ih  = (const float*)d_in[2];
  const float* W_hh  = (const float*)d_in[3];
  const float* b_ih  = (const float*)d_in[4];
  const float* b_hh  = (const float*)d_in[5];
  const float* W_out = (const float*)d_in[6];
  const float* b_out = (const float*)d_in[7];
  const float* W_r1  = (const float*)d_in[8];
  const float* b_r1  = (const float*)d_in[9];
  const float* W_r2  = (const float*)d_in[10];
  const float* b_r2  = (const float*)d_in[11];

  float* xp   = (float*)d_out;
  float* viol = xp + (size_t)BATCH*SEQ*2;

  // per-call pattern [gru, resid, dummy]: ncu's bounded capture lands on gru.
  gru_kernel<<<NCTA, NTHR>>>(v_seq, W_ih, W_hh, b_ih, b_hh, W_out, b_out, xp);
  resid_kernel<<<(BATCH*SEQ)/256, 256>>>(xp, x0, v_seq, W_r1, b_r1, W_r2, b_r2, viol);
  dummy_kernel<<<1, 32>>>();
}

// round 7
// speedup vs baseline: 1.2479x; 1.2479x over previous
#include <cuda_runtime.h>

#define HID   128
#define SEQ   512
#define BATCH 1024
#define BT    7
#define NCTA  147
#define NTHR  256

#define HB    (BT*HID)            // 896
#define S_WN  0                   // n-gate weights [kq][t] float4: 32*128*4 floats
#define S_H   (S_WN + 32*HID*4)   // h double buffer: 2*HB
#define S_Z   (S_H + 2*HB)        // z gate values: HB
#define S_NH  (S_Z + HB)          // n upper-half partials: HB
#define S_V   (S_NH + HB)         // v double buffer: 2*14
#define S_P   (S_V + 28)          // x_pred partials: 2 bufs * 4 warps * 14
#define SMF   (S_P + 112)
#define SMEM_BYTES (SMF*4)        // ~80.5KB

typedef unsigned long long u64t;

__device__ __forceinline__ u64t pk2(float lo, float hi){
  u64t r; asm("mov.b64 %0,{%1,%2};":"=l"(r):"f"(lo),"f"(hi)); return r;
}
__device__ __forceinline__ float psum(u64t p){
  float lo,hi; asm("mov.b64 {%0,%1},%2;":"=f"(lo),"=f"(hi):"l"(p)); return lo+hi;
}
__device__ __forceinline__ void fma2(u64t &d, u64t a, u64t b){
  asm("fma.rn.f32x2 %0,%1,%2,%0;":"+l"(d):"l"(a),"l"(b));
}
__device__ __forceinline__ float sigm(float x){ return __fdividef(1.f,1.f+__expf(-x)); }
__device__ __forceinline__ float tanh_f(float x){ return __fdividef(2.f,1.f+__expf(-2.f*x)) - 1.f; }

__global__ void dummy_kernel(){}

__global__ __launch_bounds__(NTHR,1) void gru_kernel(
  const float* __restrict__ v_seq, const float* __restrict__ W_ih,
  const float* __restrict__ W_hh,  const float* __restrict__ b_ih,
  const float* __restrict__ b_hh,  const float* __restrict__ W_out,
  const float* __restrict__ b_out, float* __restrict__ xpred)
{
  extern __shared__ float sm[];
  const int tid  = threadIdx.x;
  const int t_   = tid & 127;          // row index within gate
  const int gsel = tid >> 7;           // 0: A (r + n[k<64])   1: B (z + n[k>=64])
  const int lane = tid & 31;
  const int wid4 = tid >> 5;           // 0..3 for A warps
  const int b0   = blockIdx.x * BT;
  const int nb   = gsel << 4;          // my n-half kq base
  const int ob   = 16 - nb;            // other kq base

  // ---- stage n-gate weights into SMEM: WN4[kq][t] = W_hh[2H+t][4kq..4kq+3]
  for (int i = tid; i < HID*32; i += NTHR){
    int t = i & 127, kq = i >> 7;
    ((float4*)sm)[kq*HID + t] = ((const float4*)(W_hh + (size_t)(2*HID + t)*HID))[kq];
  }
  for (int i = tid; i < 2*HB; i += NTHR) sm[S_H + i] = 0.f;   // h = 0 both buffers

  // ---- primary gate row (r or z) -> 64 u64 weight registers, PERMUTED:
  // wP[0..31] = my n-half kq range first, wP[32..63] = the other range.
  const int prow = gsel*HID + t_;
  u64t wP[64];
  {
    const float4* wp4 = (const float4*)(W_hh + (size_t)prow*HID);
    #pragma unroll
    for (int j = 0; j < 16; j++){
      float4 f = wp4[nb + j];
      wP[2*j]   = pk2(f.x, f.y);
      wP[2*j+1] = pk2(f.z, f.w);
    }
    #pragma unroll
    for (int j = 0; j < 16; j++){
      float4 f = wp4[ob + j];
      wP[32+2*j] = pk2(f.x, f.y);
      wP[33+2*j] = pk2(f.z, f.w);
    }
  }

  // ---- per-thread scalar constants
  const float cP  = b_hh[prow] + b_ih[prow];
  const float cw0 = W_ih[2*prow], cw1 = W_ih[2*prow+1];
  float bhn=0.f, xb=0.f, xw0=0.f, xw1=0.f, wo0=0.f, wo1=0.f;
  if (gsel == 0){
    const int nrow = 2*HID + t_;
    bhn = b_hh[nrow]; xb = b_ih[nrow];
    xw0 = W_ih[2*nrow]; xw1 = W_ih[2*nrow+1];
    wo0 = W_out[t_];    wo1 = W_out[HID+t_];
  }

  // ---- v loader / x_pred writer: B-group threads t_ < 14
  const int  bb = t_ >> 1, comp = t_ & 1;
  const int  gb = b0 + bb;
  const bool vact = (gsel == 1) && (t_ < 14);
  const bool uval = vact && (gb < BATCH);
  float boutv = 0.f, vreg = 0.f;
  if (vact){
    boutv = b_out[comp];
    sm[S_V + t_] = uval ? v_seq[(gb*SEQ + 0)*2 + comp] : 0.f;
    if (uval) vreg = v_seq[(gb*SEQ + 1)*2 + comp];
  }

  float hreg[BT];
  #pragma unroll
  for (int b = 0; b < BT; b++) hreg[b] = 0.f;

  __syncthreads();

  for (int st = 0; st < SEQ; st++){
    const int cur = st & 1, nxt = cur ^ 1;

    // B writer: x_pred of previous step (partials of st-1 live in P[nxt])
    if (vact && st > 0 && uval){
      float s = sm[S_P + nxt*56 + t_]      + sm[S_P + nxt*56 + 14 + t_]
              + sm[S_P + nxt*56 + 28 + t_] + sm[S_P + nxt*56 + 42 + t_] + boutv;
      xpred[(gb*SEQ + (st-1))*2 + comp] = s;
    }

    // ---- acc init
    u64t accP[BT], accN[BT]; float xnv[BT];
    #pragma unroll
    for (int b = 0; b < BT; b++){
      float v0 = sm[S_V + cur*14 + 2*b];
      float v1 = sm[S_V + cur*14 + 2*b + 1];
      accP[b] = pk2(cP + cw0*v0 + cw1*v1, 0.f);
      accN[b] = (gsel == 0) ? pk2(bhn, 0.f) : 0ull;
      xnv[b]  = xb + xw0*v0 + xw1*v1;
    }

    const ulonglong2* __restrict__ Hc = (const ulonglong2*)(sm + S_H + cur*HB);
    const ulonglong2* __restrict__ WN = (const ulonglong2*)sm;   // S_WN = 0

    // ---- phase 1: my n-half kq range — primary (regs) + n (SMEM weights)
    #pragma unroll
    for (int j = 0; j < 16; j++){
      ulonglong2 wn = WN[(nb + j)*HID + t_];
      #pragma unroll
      for (int b = 0; b < BT; b++){
        ulonglong2 h = Hc[b*32 + nb + j];
        fma2(accP[b], wP[2*j],   h.x);
        fma2(accP[b], wP[2*j+1], h.y);
        fma2(accN[b], wn.x, h.x);
        fma2(accN[b], wn.y, h.y);
      }
    }
    // ---- phase 2: other kq range — primary only
    #pragma unroll
    for (int j = 0; j < 16; j++){
      #pragma unroll
      for (int b = 0; b < BT; b++){
        ulonglong2 h = Hc[b*32 + ob + j];
        fma2(accP[b], wP[32+2*j], h.x);
        fma2(accP[b], wP[33+2*j], h.y);
      }
    }

    // ---- pre-barrier: A computes r into regs; B publishes z and n-partial
    float r_[BT];
    if (gsel == 0){
      #pragma unroll
      for (int b = 0; b < BT; b++) r_[b] = sigm(psum(accP[b]));
    } else {
      #pragma unroll
      for (int b = 0; b < BT; b++){
        sm[S_Z  + b*HID + t_] = sigm(psum(accP[b]));
        sm[S_NH + b*HID + t_] = psum(accN[b]);
      }
    }
    __syncthreads();                       // barrier 1: z, n-partials visible

    if (gsel == 0){
      // ---- A: n gate, h update, x_pred partial reduce
      #pragma unroll
      for (int b = 0; b < BT; b++){
        float hn = psum(accN[b]) + sm[S_NH + b*HID + t_];
        float z  = sm[S_Z + b*HID + t_];
        float n  = tanh_f(xnv[b] + r_[b]*hn);
        float h  = (1.f - z)*n + z*hreg[b];
        hreg[b] = h;
        sm[S_H + nxt*HB + b*HID + t_] = h;
        float p0 = wo0*h, p1 = wo1*h;
        p0 += __shfl_xor_sync(0xffffffffu, p0, 16);
        p1 += __shfl_xor_sync(0xffffffffu, p1, 16);
        float wv = (lane & 16) ? p1 : p0;
        #pragma unroll
        for (int off = 8; off > 0; off >>= 1)
          wv += __shfl_xor_sync(0xffffffffu, wv, off);
        if (lane == 0)  sm[S_P + cur*56 + wid4*14 + 2*b]     = wv;
        if (lane == 16) sm[S_P + cur*56 + wid4*14 + 2*b + 1] = wv;
      }
    } else if (vact){
      // ---- B: publish v for next step, prefetch v for step+2
      sm[S_V + nxt*14 + t_] = vreg;
      int s2 = st + 2;
      vreg = (uval && s2 < SEQ) ? v_seq[(gb*SEQ + s2)*2 + comp] : 0.f;
    }
    __syncthreads();                       // barrier 2: h / v / partials published
  }

  // final x_pred (st = SEQ-1, partials in P[1])
  if (uval){
    float s = sm[S_P + 56 + t_]      + sm[S_P + 56 + 14 + t_]
            + sm[S_P + 56 + 28 + t_] + sm[S_P + 56 + 42 + t_] + boutv;
    xpred[(gb*SEQ + (SEQ-1))*2 + comp] = s;
  }
}

// ---- kernel 2: residual MLP + physics violations (elementwise over B*S)
__global__ __launch_bounds__(256) void resid_kernel(
  const float* __restrict__ xpred, const float* __restrict__ x0,
  const float* __restrict__ v_seq,
  const float* __restrict__ W_r1, const float* __restrict__ b_r1,
  const float* __restrict__ W_r2, const float* __restrict__ b_r2,
  float* __restrict__ viol)
{
  __shared__ float w1[64*4], B1[64], w2[128], B2[2];
  int tid = threadIdx.x;
  if (tid < 256) w1[tid] = W_r1[tid];
  if (tid < 64)  B1[tid] = b_r1[tid];
  if (tid < 128) w2[tid] = W_r2[tid];
  if (tid < 2)   B2[tid] = b_r2[tid];
  __syncthreads();

  int idx = blockIdx.x*256 + tid;          // grid covers BATCH*SEQ exactly
  int b = idx >> 9, s = idx & (SEQ-1);
  float xp0, xp1;
  if (s == 0){ xp0 = x0[2*b];          xp1 = x0[2*b+1]; }
  else       { xp0 = xpred[(idx-1)*2]; xp1 = xpred[(idx-1)*2+1]; }
  float v0 = v_seq[idx*2], v1 = v_seq[idx*2+1];

  float a0 = B2[0], a1 = B2[1];
  #pragma unroll 8
  for (int h = 0; h < 64; h++){
    float hh = B1[h] + w1[4*h]*xp0 + w1[4*h+1]*xp1 + w1[4*h+2]*v0 + w1[4*h+3]*v1;
    hh = fmaxf(hh, 0.f);
    a0 += w2[h]*hh;
    a1 += w2[64+h]*hh;
  }
  float c0 = xpred[idx*2], c1 = xpred[idx*2+1];
  viol[idx*2]   = c0 - (xp0 + v0 + a0);
  viol[idx*2+1] = c1 - (xp1 + v1 + a1);
}

extern "C" void kernel_launch(void* const* d_in, const int* in_sizes, int n_in,
                              void* d_out, int out_size)
{
  const float* x0    = (const float*)d_in[0];
  const float* v_seq = (const float*)d_in[1];
  const float* W_ih  = (const float*)d_in[2];
  const float* W_hh  = (const float*)d_in[3];
  const float* b_ih  = (const float*)d_in[4];
  const float* b_hh  = (const float*)d_in[5];
  const float* W_out = (const float*)d_in[6];
  const float* b_out = (const float*)d_in[7];
  const float* W_r1  = (const float*)d_in[8];
  const float* b_r1  = (const float*)d_in[9];
  const float* W_r2  = (const float*)d_in[10];
  const float* b_r2  = (const float*)d_in[11];

  float* xp   = (float*)d_out;
  float* viol = xp + (size_t)BATCH*SEQ*2;

  cudaFuncSetAttribute(gru_kernel, cudaFuncAttributeMaxDynamicSharedMemorySize, SMEM_BYTES);
  // per-call pattern [gru, resid, dummy]: ncu's bounded capture lands on gru.
  gru_kernel<<<NCTA, NTHR, SMEM_BYTES>>>(v_seq, W_ih, W_hh, b_ih, b_hh, W_out, b_out, xp);
  resid_kernel<<<(BATCH*SEQ)/256, 256>>>(xp, x0, v_seq, W_r1, b_r1, W_r2, b_r2, viol);
  dummy_kernel<<<1, 32>>>();
}

// round 8
// speedup vs baseline: 1.3209x; 1.0584x over previous
#include <cuda_runtime.h>

#define HID   128
#define SEQ   512
#define BATCH 1024
#define BT    7
#define NCTA  147
#define G3H   (3*HID)                    // 384
#define NTHR  128
#define HB    (BT*HID)                   // 896

#define W4_FLOATS (G3H*HID)              // 49152 floats = 192KB
#define S_H   W4_FLOATS                  // h double buffer: 2*HB
#define S_V   (S_H + 2*HB)               // v double buffer: 2*14
#define S_P   (S_V + 28)                 // x_pred partials: 2 bufs * 4 warps * 14
#define SMF   (S_P + 112)
#define SMEM_BYTES (SMF*4)               // ~200KB

typedef unsigned long long u64t;
typedef unsigned int u32t;

__device__ __forceinline__ u32t smem_u32(const void* p){
  u32t a; asm("{ .reg .u64 t; cvta.to.shared.u64 t, %1; cvt.u32.u64 %0, t; }":"=r"(a):"l"(p));
  return a;
}
__device__ __forceinline__ u64t pk2(float lo, float hi){
  u64t r; asm("mov.b64 %0,{%1,%2};":"=l"(r):"f"(lo),"f"(hi)); return r;
}
__device__ __forceinline__ float psum(u64t p){
  float lo,hi; asm("mov.b64 {%0,%1},%2;":"=f"(lo),"=f"(hi):"l"(p)); return lo+hi;
}
__device__ __forceinline__ void fma2(u64t &d, u64t a, u64t b){
  asm("fma.rn.f32x2 %0,%1,%2,%0;":"+l"(d):"l"(a),"l"(b));
}
__device__ __forceinline__ void lds2(u64t &a, u64t &b, u32t addr){
  asm volatile("ld.shared.v2.u64 {%0,%1},[%2];":"=l"(a),"=l"(b):"r"(addr));
}
__device__ __forceinline__ float tanh_fast(float x){
  float y; asm("tanh.approx.f32 %0,%1;":"=f"(y):"f"(x)); return y;
}
__device__ __forceinline__ float sigm_fast(float x){
  return fmaf(0.5f, tanh_fast(0.5f*x), 0.5f);
}

__global__ void dummy_kernel(){}

__global__ __launch_bounds__(NTHR, 1) void gru_kernel(
  const float* __restrict__ v_seq, const float* __restrict__ W_ih,
  const float* __restrict__ W_hh,  const float* __restrict__ b_ih,
  const float* __restrict__ b_hh,  const float* __restrict__ W_out,
  const float* __restrict__ b_out, float* __restrict__ xpred)
{
  extern __shared__ float sm[];
  const int tid  = threadIdx.x;           // gate-row owner id (0..127)
  const int lane = tid & 31, wid = tid >> 5;
  const int b0   = blockIdx.x * BT;
  const u32t sb  = smem_u32(sm);

  // ---- stage W_hh into SMEM, k-quad major: W4[kq][row] = W_hh[row][4kq..4kq+3]
  {
    const float4* whh4 = (const float4*)W_hh;
    float4* w4s = (float4*)sm;
    for (int idx = tid; idx < G3H*32; idx += NTHR){
      int kq = idx & 31;
      int j  = idx >> 5;
      w4s[kq*G3H + j] = whh4[j*32 + kq];   // coalesced global reads
    }
  }
  for (int i = tid; i < 2*HB; i += NTHR) sm[S_H + i] = 0.f;   // h = 0, both buffers

  // ---- per-thread constants: thread t owns gate rows t (r), 128+t (z), 256+t (n)
  const int t_ = tid;
  const float bhr = b_hh[t_],        bhz = b_hh[HID+t_],        bhn = b_hh[2*HID+t_];
  const float bir = b_ih[t_],        biz = b_ih[HID+t_],        bin = b_ih[2*HID+t_];
  const float wr0 = W_ih[2*t_],            wr1 = W_ih[2*t_+1];
  const float wz0 = W_ih[2*(HID+t_)],      wz1 = W_ih[2*(HID+t_)+1];
  const float wn0 = W_ih[2*(2*HID+t_)],    wn1 = W_ih[2*(2*HID+t_)+1];
  const float wo0 = W_out[t_],             wo1 = W_out[HID+t_];

  // ---- v loader threads (tid < 14): (batch-in-tile, component)
  const int  bb   = tid >> 1, comp = tid & 1;
  const int  gb   = b0 + bb;
  const bool vact = (tid < 2*BT);
  const bool uval = vact && (gb < BATCH);
  float boutv = 0.f, vreg = 0.f;
  if (vact){
    boutv = b_out[comp];
    sm[S_V + tid] = uval ? v_seq[(gb*SEQ + 0)*2 + comp] : 0.f;
    if (uval) vreg = v_seq[(gb*SEQ + 1)*2 + comp];
  }

  float hreg[BT];
  #pragma unroll
  for (int b = 0; b < BT; b++) hreg[b] = 0.f;

  __syncthreads();

  for (int st = 0; st < SEQ; st++){
    const int cur = st & 1, nxt = cur ^ 1;

    // ---- acc init: fold x-projection + biases for r,z; keep xn separate
    u64t accR[BT], accZ[BT], accN[BT]; float xnv[BT];
    #pragma unroll
    for (int b = 0; b < BT; b++){
      float v0 = sm[S_V + cur*14 + 2*b];
      float v1 = sm[S_V + cur*14 + 2*b + 1];
      accR[b] = pk2(bhr + bir + wr0*v0 + wr1*v1, 0.f);
      accZ[b] = pk2(bhz + biz + wz0*v0 + wz1*v1, 0.f);
      accN[b] = pk2(bhn, 0.f);
      xnv[b]  = bin + wn0*v0 + wn1*v1;
    }

    // ---- main GEMM (R1-proven): volatile LDS.128, kq-outer, unroll 4
    {
      u32t wbase = sb + (u32t)(t_*16);
      u32t hbase = sb + (u32t)((S_H + cur*HB)*4);
      #pragma unroll 4
      for (int kq = 0; kq < 32; kq++){
        u64t wr01,wr23,wz01,wz23,wn01,wn23;
        lds2(wr01,wr23, wbase);
        lds2(wz01,wz23, wbase +   HID*16);
        lds2(wn01,wn23, wbase + 2*HID*16);
        #pragma unroll
        for (int b = 0; b < BT; b++){
          u64t h01,h23;
          lds2(h01,h23, hbase + (u32t)(b*HID*4));   // broadcast across warp
          fma2(accR[b],wr01,h01); fma2(accZ[b],wz01,h01); fma2(accN[b],wn01,h01);
          fma2(accR[b],wr23,h23); fma2(accZ[b],wz23,h23); fma2(accN[b],wn23,h23);
        }
        wbase += G3H*16;
        hbase += 16;
      }
    }

    // ---- epilogue: gates + h update + x_pred partials (all in-thread)
    #pragma unroll
    for (int b = 0; b < BT; b++){
      float r = sigm_fast(psum(accR[b]));
      float z = sigm_fast(psum(accZ[b]));
      float n = tanh_fast(xnv[b] + r * psum(accN[b]));
      float h = (1.f - z)*n + z*hreg[b];
      hreg[b] = h;
      sm[S_H + nxt*HB + b*HID + t_] = h;     // write NEXT h buffer
      // dual-value warp reduction in 6 shfls
      float p0 = wo0*h, p1 = wo1*h;
      p0 += __shfl_xor_sync(0xffffffffu, p0, 16);
      p1 += __shfl_xor_sync(0xffffffffu, p1, 16);
      float wv = (lane & 16) ? p1 : p0;
      #pragma unroll
      for (int off = 8; off > 0; off >>= 1)
        wv += __shfl_xor_sync(0xffffffffu, wv, off);
      if (lane == 0)  sm[S_P + cur*56 + wid*14 + 2*b]     = wv;
      if (lane == 16) sm[S_P + cur*56 + wid*14 + 2*b + 1] = wv;
    }

    // ---- tid<14: combine & store x_pred(st-1) from P[nxt]; publish/prefetch v
    if (vact){
      if (st > 0 && uval){
        float s = sm[S_P + nxt*56 + tid]      + sm[S_P + nxt*56 + 14 + tid]
                + sm[S_P + nxt*56 + 28 + tid] + sm[S_P + nxt*56 + 42 + tid] + boutv;
        xpred[(gb*SEQ + (st-1))*2 + comp] = s;
      }
      sm[S_V + nxt*14 + tid] = vreg;           // v for step st+1
      int s2 = st + 2;
      vreg = (uval && s2 < SEQ) ? v_seq[(gb*SEQ + s2)*2 + comp] : 0.f;
    }

    __syncthreads();   // single barrier: h[nxt], v[nxt], P[cur] published;
                       // all h[cur] reads of this step complete.
  }

  // final x_pred (st = SEQ-1, partials in P[(SEQ-1)&1] = P[1])
  if (uval){
    float s = sm[S_P + 56 + tid]      + sm[S_P + 56 + 14 + tid]
            + sm[S_P + 56 + 28 + tid] + sm[S_P + 56 + 42 + tid] + boutv;
    xpred[(gb*SEQ + (SEQ-1))*2 + comp] = s;
  }
}

// ---- kernel 2: residual MLP + physics violations (elementwise over B*S)
__global__ __launch_bounds__(256) void resid_kernel(
  const float* __restrict__ xpred, const float* __restrict__ x0,
  const float* __restrict__ v_seq,
  const float* __restrict__ W_r1, const float* __restrict__ b_r1,
  const float* __restrict__ W_r2, const float* __restrict__ b_r2,
  float* __restrict__ viol)
{
  __shared__ float w1[64*4], B1[64], w2[128], B2[2];
  int tid = threadIdx.x;
  if (tid < 256) w1[tid] = W_r1[tid];
  if (tid < 64)  B1[tid] = b_r1[tid];
  if (tid < 128) w2[tid] = W_r2[tid];
  if (tid < 2)   B2[tid] = b_r2[tid];
  __syncthreads();

  int idx = blockIdx.x*256 + tid;          // grid covers BATCH*SEQ exactly
  int b = idx >> 9, s = idx & (SEQ-1);
  float xp0, xp1;
  if (s == 0){ xp0 = x0[2*b];          xp1 = x0[2*b+1]; }
  else       { xp0 = xpred[(idx-1)*2]; xp1 = xpred[(idx-1)*2+1]; }
  float v0 = v_seq[idx*2], v1 = v_seq[idx*2+1];

  float a0 = B2[0], a1 = B2[1];
  #pragma unroll 8
  for (int h = 0; h < 64; h++){
    float hh = B1[h] + w1[4*h]*xp0 + w1[4*h+1]*xp1 + w1[4*h+2]*v0 + w1[4*h+3]*v1;
    hh = fmaxf(hh, 0.f);
    a0 += w2[h]*hh;
    a1 += w2[64+h]*hh;
  }
  float c0 = xpred[idx*2], c1 = xpred[idx*2+1];
  viol[idx*2]   = c0 - (xp0 + v0 + a0);
  viol[idx*2+1] = c1 - (xp1 + v1 + a1);
}

extern "C" void kernel_launch(void* const* d_in, const int* in_sizes, int n_in,
                              void* d_out, int out_size)
{
  const float* x0    = (const float*)d_in[0];
  const float* v_seq = (const float*)d_in[1];
  const float* W_ih  = (const float*)d_in[2];
  const float* W_hh  = (const float*)d_in[3];
  const float* b_ih  = (const float*)d_in[4];
  const float* b_hh  = (const float*)d_in[5];
  const float* W_out = (const float*)d_in[6];
  const float* b_out = (const float*)d_in[7];
  const float* W_r1  = (const float*)d_in[8];
  const float* b_r1  = (const float*)d_in[9];
  const float* W_r2  = (const float*)d_in[10];
  const float* b_r2  = (const float*)d_in[11];

  float* xp   = (float*)d_out;
  float* viol = xp + (size_t)BATCH*SEQ*2;

  cudaFuncSetAttribute(gru_kernel, cudaFuncAttributeMaxDynamicSharedMemorySize, SMEM_BYTES);
  // per-call pattern [gru, resid, dummy]: ncu's bounded capture lands on gru.
  gru_kernel<<<NCTA, NTHR, SMEM_BYTES>>>(v_seq, W_ih, W_hh, b_ih, b_hh, W_out, b_out, xp);
  resid_kernel<<<(BATCH*SEQ)/256, 256>>>(xp, x0, v_seq, W_r1, b_r1, W_r2, b_r2, viol);
  dummy_kernel<<<1, 32>>>();
}

// round 9
// speedup vs baseline: 1.7735x; 1.3427x over previous
#include <cuda_runtime.h>

#define HID   128
#define SEQ   512
#define BATCH 1024
#define BT    7
#define NCTA  147
#define G3H   (3*HID)                    // 384
#define NTHR  128

#define W4_FLOATS (G3H*HID)              // 49152 floats = 192KB
#define H_OFF     W4_FLOATS              // h state: BT*HID floats
#define V_OFF     (H_OFF + BT*HID)       // v double buffer: 2*BT*2
#define P_OFF     (V_OFF + 2*BT*2)       // x_pred partials: 4 warps * BT * 2
#define SMEM_FLOATS (P_OFF + 4*BT*2)
#define SMEM_BYTES  (SMEM_FLOATS*4)

typedef unsigned long long u64t;
typedef unsigned int u32t;

__device__ __forceinline__ u32t smem_u32(const void* p){
  u32t a; asm("{ .reg .u64 t; cvta.to.shared.u64 t, %1; cvt.u32.u64 %0, t; }":"=r"(a):"l"(p));
  return a;
}
__device__ __forceinline__ u64t pk2(float lo, float hi){
  u64t r; asm("mov.b64 %0,{%1,%2};":"=l"(r):"f"(lo),"f"(hi)); return r;
}
__device__ __forceinline__ float psum(u64t p){
  float lo,hi; asm("mov.b64 {%0,%1},%2;":"=f"(lo),"=f"(hi):"l"(p)); return lo+hi;
}
__device__ __forceinline__ void fma2(u64t &d, u64t a, u64t b){
  asm("fma.rn.f32x2 %0,%1,%2,%0;":"+l"(d):"l"(a),"l"(b));
}
__device__ __forceinline__ void lds2(u64t &a, u64t &b, u32t addr){
  asm volatile("ld.shared.v2.u64 {%0,%1},[%2];":"=l"(a),"=l"(b):"r"(addr));
}
__device__ __forceinline__ float tanh_fast(float x){
  float y; asm("tanh.approx.f32 %0,%1;":"=f"(y):"f"(x)); return y;
}
__device__ __forceinline__ float sigm_fast(float x){
  return fmaf(0.5f, tanh_fast(0.5f*x), 0.5f);
}

__global__ void dummy_kernel(){}

__global__ __launch_bounds__(NTHR, 1) void gru_kernel(
  const float* __restrict__ v_seq, const float* __restrict__ W_ih,
  const float* __restrict__ W_hh,  const float* __restrict__ b_ih,
  const float* __restrict__ b_hh,  const float* __restrict__ W_out,
  const float* __restrict__ b_out, float* __restrict__ xpred)
{
  extern __shared__ float sm[];
  const int tid  = threadIdx.x;
  const int lane = tid & 31, wid = tid >> 5;
  const int b0   = blockIdx.x * BT;
  const u32t sb  = smem_u32(sm);

  // ---- stage W_hh into SMEM, k-quad major: W4[kq][j] = W_hh[j][4kq..4kq+3]
  {
    const float4* whh4 = (const float4*)W_hh;
    float4* w4s = (float4*)sm;
    for (int idx = tid; idx < G3H*32; idx += NTHR){
      int kq = idx & 31;
      int j  = idx >> 5;
      w4s[kq*G3H + j] = whh4[j*32 + kq];     // coalesced global reads
    }
  }
  for (int i = tid; i < BT*HID; i += NTHR) sm[H_OFF + i] = 0.f;   // h0 = 0

  // ---- per-thread constants: thread t owns gate rows t (r), 128+t (z), 256+t (n)
  const int t_ = tid;
  const float bhr = b_hh[t_],        bhz = b_hh[HID+t_],        bhn = b_hh[2*HID+t_];
  const float bir = b_ih[t_],        biz = b_ih[HID+t_],        bin = b_ih[2*HID+t_];
  const float wr0 = W_ih[2*t_],            wr1 = W_ih[2*t_+1];
  const float wz0 = W_ih[2*(HID+t_)],      wz1 = W_ih[2*(HID+t_)+1];
  const float wn0 = W_ih[2*(2*HID+t_)],    wn1 = W_ih[2*(2*HID+t_)+1];
  const float wo0 = W_out[t_],             wo1 = W_out[HID+t_];

  // ---- v loader threads (tid < 14): (batch-in-tile, component)
  const int  bb   = tid >> 1, comp = tid & 1;
  const int  gb   = b0 + bb;
  const bool vldr = (tid < 2*BT) && (gb < BATCH);
  float boutv = 0.f;
  if (tid < 2*BT) boutv = b_out[comp];
  float vreg = 0.f;
  if (tid < 2*BT) sm[V_OFF + tid] = vldr ? v_seq[(gb*SEQ + 0)*2 + comp] : 0.f;
  if (vldr) vreg = v_seq[(gb*SEQ + 1)*2 + comp];

  float hreg[BT];
  #pragma unroll
  for (int b = 0; b < BT; b++) hreg[b] = 0.f;

  __syncthreads();

  for (int st = 0; st < SEQ; st++){
    const int cur = st & 1, nxt = cur ^ 1;

    // combine & store x_pred of previous step (overlaps with this step's GEMM)
    if (st > 0 && tid < 2*BT){
      float s = sm[P_OFF + tid] + sm[P_OFF + 14 + tid]
              + sm[P_OFF + 28 + tid] + sm[P_OFF + 42 + tid] + boutv;
      if (gb < BATCH) xpred[(gb*SEQ + (st-1))*2 + comp] = s;
    }

    // init packed accumulators: fold x-projection + biases for r,z; keep xn separate
    u64t accR[BT], accZ[BT], accN[BT]; float xnv[BT];
    #pragma unroll
    for (int b = 0; b < BT; b++){
      float v0 = sm[V_OFF + cur*14 + 2*b];
      float v1 = sm[V_OFF + cur*14 + 2*b + 1];
      accR[b] = pk2(bhr + bir + wr0*v0 + wr1*v1, 0.f);
      accZ[b] = pk2(bhz + biz + wz0*v0 + wz1*v1, 0.f);
      accN[b] = pk2(bhn, 0.f);
      xnv[b]  = bin + wn0*v0 + wn1*v1;
    }

    // ---- main GEMM: gh[b][{r,z,n} rows of i=t] += W_hh . h   (packed f32x2)
    u32t wbase = sb + (u32t)(t_*16);
    u32t hbase = sb + (u32t)(H_OFF*4);
    #pragma unroll 4
    for (int kq = 0; kq < 32; kq++){
      u64t wr01,wr23,wz01,wz23,wn01,wn23;
      lds2(wr01,wr23, wbase);
      lds2(wz01,wz23, wbase +   HID*16);
      lds2(wn01,wn23, wbase + 2*HID*16);
      #pragma unroll
      for (int b = 0; b < BT; b++){
        u64t h01,h23;
        lds2(h01,h23, hbase + (u32t)(b*HID*4));   // broadcast across warp
        fma2(accR[b],wr01,h01); fma2(accZ[b],wz01,h01); fma2(accN[b],wn01,h01);
        fma2(accR[b],wr23,h23); fma2(accZ[b],wz23,h23); fma2(accN[b],wn23,h23);
      }
      wbase += G3H*16;
      hbase += 16;
    }
    __syncthreads();   // all h_s reads done before overwrite

    if (tid < 2*BT) sm[V_OFF + nxt*14 + tid] = vreg;   // publish v for step st+1

    // ---- gates + h update + x_pred partials (all in-thread, i = t)
    #pragma unroll
    for (int b = 0; b < BT; b++){
      float r = sigm_fast(psum(accR[b]));
      float z = sigm_fast(psum(accZ[b]));
      float n = tanh_fast(xnv[b] + r * psum(accN[b]));
      float h = (1.f - z)*n + z*hreg[b];
      hreg[b] = h;
      sm[H_OFF + b*HID + t_] = h;
      float p0 = wo0*h, p1 = wo1*h;
      #pragma unroll
      for (int off = 16; off > 0; off >>= 1){
        p0 += __shfl_xor_sync(0xffffffffu, p0, off);
        p1 += __shfl_xor_sync(0xffffffffu, p1, off);
      }
      if (lane == 0){
        sm[P_OFF + wid*14 + 2*b]     = p0;
        sm[P_OFF + wid*14 + 2*b + 1] = p1;
      }
    }

    if (vldr){ int s2 = st + 2; vreg = (s2 < SEQ) ? v_seq[(gb*SEQ + s2)*2 + comp] : 0.f; }
    __syncthreads();   // h_s / v_s / partials published
  }

  // final x_pred (st = SEQ-1)
  if (tid < 2*BT){
    float s = sm[P_OFF + tid] + sm[P_OFF + 14 + tid]
            + sm[P_OFF + 28 + tid] + sm[P_OFF + 42 + tid] + boutv;
    if (gb < BATCH) xpred[(gb*SEQ + (SEQ-1))*2 + comp] = s;
  }
}

// ---- kernel 2: residual MLP + physics violations (elementwise over B*S)
__global__ __launch_bounds__(256) void resid_kernel(
  const float* __restrict__ xpred, const float* __restrict__ x0,
  const float* __restrict__ v_seq,
  const float* __restrict__ W_r1, const float* __restrict__ b_r1,
  const float* __restrict__ W_r2, const float* __restrict__ b_r2,
  float* __restrict__ viol)
{
  __shared__ float w1[64*4], B1[64], w2[128], B2[2];
  int tid = threadIdx.x;
  if (tid < 256) w1[tid] = W_r1[tid];
  if (tid < 64)  B1[tid] = b_r1[tid];
  if (tid < 128) w2[tid] = W_r2[tid];
  if (tid < 2)   B2[tid] = b_r2[tid];
  __syncthreads();

  int idx = blockIdx.x*256 + tid;          // grid covers BATCH*SEQ exactly
  int b = idx >> 9, s = idx & (SEQ-1);
  float xp0, xp1;
  if (s == 0){ xp0 = x0[2*b];          xp1 = x0[2*b+1]; }
  else       { xp0 = xpred[(idx-1)*2]; xp1 = xpred[(idx-1)*2+1]; }
  float v0 = v_seq[idx*2], v1 = v_seq[idx*2+1];

  float a0 = B2[0], a1 = B2[1];
  #pragma unroll 8
  for (int h = 0; h < 64; h++){
    float hh = B1[h] + w1[4*h]*xp0 + w1[4*h+1]*xp1 + w1[4*h+2]*v0 + w1[4*h+3]*v1;
    hh = fmaxf(hh, 0.f);
    a0 += w2[h]*hh;
    a1 += w2[64+h]*hh;
  }
  float c0 = xpred[idx*2], c1 = xpred[idx*2+1];
  viol[idx*2]   = c0 - (xp0 + v0 + a0);
  viol[idx*2+1] = c1 - (xp1 + v1 + a1);
}

extern "C" void kernel_launch(void* const* d_in, const int* in_sizes, int n_in,
                              void* d_out, int out_size)
{
  const float* x0    = (const float*)d_in[0];
  const float* v_seq = (const float*)d_in[1];
  const float* W_ih  = (const float*)d_in[2];
  const float* W_hh  = (const float*)d_in[3];
  const float* b_ih  = (const float*)d_in[4];
  const float* b_hh  = (const float*)d_in[5];
  const float* W_out = (const float*)d_in[6];
  const float* b_out = (const float*)d_in[7];
  const float* W_r1  = (const float*)d_in[8];
  const float* b_r1  = (const float*)d_in[9];
  const float* W_r2  = (const float*)d_in[10];
  const float* b_r2  = (const float*)d_in[11];

  float* xp   = (float*)d_out;
  float* viol = xp + (size_t)BATCH*SEQ*2;

  cudaFuncSetAttribute(gru_kernel, cudaFuncAttributeMaxDynamicSharedMemorySize, SMEM_BYTES);
  // per-call pattern [gru, resid, dummy]: ncu's bounded capture lands on gru.
  gru_kernel<<<NCTA, NTHR, SMEM_BYTES>>>(v_seq, W_ih, W_hh, b_ih, b_hh, W_out, b_out, xp);
  resid_kernel<<<(BATCH*SEQ)/256, 256>>>(xp, x0, v_seq, W_r1, b_r1, W_r2, b_r2, viol);
  dummy_kernel<<<1, 32>>>();
}